// round 5
// baseline (speedup 1.0000x reference)
#include <cuda_runtime.h>
#include <math.h>

#define NMAX 100000
#define MM_GRID 1184

// Scratch (device globals: zero-initialized at module load; every launch
// leaves them zeroed again, so no zero-pass kernel is needed).
__device__ __align__(16) float g_aggp[NMAX * 64];
__device__ __align__(16) float g_aggn[NMAX * 64];
__device__ __align__(16) float g_degp[NMAX];
__device__ __align__(16) float g_degn[NMAX];
__device__ __align__(16) float g_z[NMAX * 64];

// ---------------------------------------------------------------------------
// Weighted scatter aggregation, pos+neg fused in one grid: 16 threads/edge,
// float4 per thread.  sum[dst] += feat[src]*w ; (round 1 only) deg[dst] += w.
// red.global.add.v4.f32 (sm_90+): 4x fewer atomic instructions, no return.
// Edges [0,Ep) are positive, [Ep,Ep+En) negative; branch is block-granular.
// deg depends only on weights/topology, so round 2 skips it (do_deg=0).
// ---------------------------------------------------------------------------
__global__ void agg_kernel(const int* __restrict__ pei, const int* __restrict__ nei,
                           const float* __restrict__ pw, const float* __restrict__ nw,
                           const float* __restrict__ feat,
                           float* __restrict__ aggp, float* __restrict__ aggn,
                           float* __restrict__ degp, float* __restrict__ degn,
                           int Ep, int En, int do_deg) {
    int tid = blockIdx.x * blockDim.x + threadIdx.x;
    int e = tid >> 4;
    if (e >= Ep + En) return;
    int t = tid & 15;

    const int* ei; const float* wgt; float* sum; float* deg; int E;
    if (e < Ep) { ei = pei; wgt = pw; sum = aggp; deg = degp; E = Ep; }
    else        { e -= Ep; ei = nei; wgt = nw; sum = aggn; deg = degn; E = En; }

    int s = ei[e];
    int d = ei[e + E];
    float w = __ldg(wgt + e);
    float4 v = *(const float4*)(feat + s * 64 + t * 4);
    float a = v.x * w, b = v.y * w, c = v.z * w, dd = v.w * w;
    float* p = sum + d * 64 + t * 4;
    asm volatile("red.global.add.v4.f32 [%0], {%1,%2,%3,%4};"
                 :: "l"(p), "f"(a), "f"(b), "f"(c), "f"(dd) : "memory");
    if (do_deg && t == 0) {
        asm volatile("red.global.add.f32 [%0], %1;"
                     :: "l"(deg + d), "f"(w) : "memory");
    }
}

// ---------------------------------------------------------------------------
// Layer 1: zp = [ap|x] @ w1p + b1p, zn = [an|x] @ w1n + b1n,
//          z = tanh([zp|zn]) -> g_z. Re-zeroes agg buffers for round 2
//          (deg is kept: round 2 reuses it, layer2 zeroes it).
// Mapping: 16-node tiles; warp w -> (node group g=w>>1 of 4 nodes, half=w&1);
// lane j computes output j of its half for all 4 nodes of the group.
// Per float4 step: 1 spread weight LDS.128 (4 wf) + 4 broadcast input
// LDS.128 (4 wf) per 16 FFMA-instr -> smem/FMA balanced (8 wf vs 8 cyc).
// Weight rows padded to 132 floats (132 mod 32 = 4 -> conflict-free quads).
// ---------------------------------------------------------------------------
__global__ void __launch_bounds__(256) layer1_kernel(
    const float* __restrict__ x,
    const float* __restrict__ w1p, const float* __restrict__ b1p,
    const float* __restrict__ w1n, const float* __restrict__ b1n,
    int n)
{
    __shared__ __align__(16) float s_wp[32 * 132];
    __shared__ __align__(16) float s_wn[32 * 132];
    __shared__ __align__(16) float s_b[64];
    __shared__ __align__(16) float s_ap[16][64];
    __shared__ __align__(16) float s_an[16][64];
    __shared__ __align__(16) float s_x[16][64];
    __shared__ float s_ip[16], s_iq[16];

    int tid = threadIdx.x;
    for (int idx = tid; idx < 128 * 32; idx += 256) {
        int i = idx >> 5, j = idx & 31;
        s_wp[j * 132 + i] = w1p[idx];
        s_wn[j * 132 + i] = w1n[idx];
    }
    if (tid < 32) { s_b[tid] = b1p[tid]; s_b[32 + tid] = b1n[tid]; }
    __syncthreads();

    int ntiles = (n + 15) >> 4;
    int warp = tid >> 5, lane = tid & 31;
    int grp = warp >> 1, half = warp & 1;

    for (int tile = blockIdx.x; tile < ntiles; tile += gridDim.x) {
        int n0 = tile * 16;
        // Phase A: inverse degrees (single reader per value)
        if (tid < 16) {
            int node = n0 + tid;
            if (node < n) {
                s_ip[tid] = 1.0f / fmaxf(g_degp[node], 1e-12f);
                s_iq[tid] = 1.0f / fmaxf(g_degn[node], 1e-12f);
            }
        }
        __syncthreads();
        // Phase B: stage scaled agg + x; zero agg (NOT deg) for round 2
        for (int idx = tid; idx < 16 * 64; idx += 256) {
            int nn = idx >> 6, k = idx & 63;
            int node = n0 + nn;
            if (node < n) {
                int o = node * 64 + k;
                s_ap[nn][k] = g_aggp[o] * s_ip[nn];  g_aggp[o] = 0.f;
                s_an[nn][k] = g_aggn[o] * s_iq[nn];  g_aggn[o] = 0.f;
                s_x[nn][k]  = x[o];
            }
        }
        __syncthreads();

        {
            const float* row = (half ? s_wn : s_wp) + lane * 132;
            const float (*inA)[64] = half ? s_an : s_ap;
            int nb = grp * 4;
            float acc0 = s_b[half * 32 + lane];
            float acc1 = acc0, acc2 = acc0, acc3 = acc0;
            #pragma unroll
            for (int i = 0; i < 64; i += 4) {
                float4 wv = *(const float4*)(row + i);
                float4 v0 = *(const float4*)(&inA[nb + 0][i]);
                float4 v1 = *(const float4*)(&inA[nb + 1][i]);
                float4 v2 = *(const float4*)(&inA[nb + 2][i]);
                float4 v3 = *(const float4*)(&inA[nb + 3][i]);
                acc0 += wv.x * v0.x + wv.y * v0.y + wv.z * v0.z + wv.w * v0.w;
                acc1 += wv.x * v1.x + wv.y * v1.y + wv.z * v1.z + wv.w * v1.w;
                acc2 += wv.x * v2.x + wv.y * v2.y + wv.z * v2.z + wv.w * v2.w;
                acc3 += wv.x * v3.x + wv.y * v3.y + wv.z * v3.z + wv.w * v3.w;
            }
            #pragma unroll
            for (int i = 0; i < 64; i += 4) {
                float4 wv = *(const float4*)(row + 64 + i);
                float4 v0 = *(const float4*)(&s_x[nb + 0][i]);
                float4 v1 = *(const float4*)(&s_x[nb + 1][i]);
                float4 v2 = *(const float4*)(&s_x[nb + 2][i]);
                float4 v3 = *(const float4*)(&s_x[nb + 3][i]);
                acc0 += wv.x * v0.x + wv.y * v0.y + wv.z * v0.z + wv.w * v0.w;
                acc1 += wv.x * v1.x + wv.y * v1.y + wv.z * v1.z + wv.w * v1.w;
                acc2 += wv.x * v2.x + wv.y * v2.y + wv.z * v2.z + wv.w * v2.w;
                acc3 += wv.x * v3.x + wv.y * v3.y + wv.z * v3.z + wv.w * v3.w;
            }
            int jo = half * 32 + lane;
            if (n0 + nb + 0 < n) g_z[(n0 + nb + 0) * 64 + jo] = tanhf(acc0);
            if (n0 + nb + 1 < n) g_z[(n0 + nb + 1) * 64 + jo] = tanhf(acc1);
            if (n0 + nb + 2 < n) g_z[(n0 + nb + 2) * 64 + jo] = tanhf(acc2);
            if (n0 + nb + 3 < n) g_z[(n0 + nb + 3) * 64 + jo] = tanhf(acc3);
        }
        __syncthreads();
    }
}

// ---------------------------------------------------------------------------
// Layer 2 + output layer, fused.
//  op = [aggpos(zp) | aggneg(zn) | zp] @ w2p + b2p
//  on = [aggpos(zn) | aggneg(zp) | zn] @ w2n + b2n
//  z2 = tanh([op|on]);  out = tanh(z2 @ wout + bout)
// The second agg pass aggregated the FULL 64-d z once per sign, so the four
// 32-d aggregations of the reference are column slices of g_aggp/g_aggn.
// Staging zeroes agg+deg after reading (restores launch-entry invariant
// for graph replay; each (h,i) slot maps to a distinct element -> race-free).
// Same 4-node register blocking as layer 1.
// ---------------------------------------------------------------------------
__global__ void __launch_bounds__(256) layer2_kernel(
    const float* __restrict__ w2p, const float* __restrict__ b2p,
    const float* __restrict__ w2n, const float* __restrict__ b2n,
    const float* __restrict__ wout, const float* __restrict__ bout,
    float* __restrict__ out, int n)
{
    __shared__ __align__(16) float s_wp[32 * 100];   // w2pT rows padded to 100
    __shared__ __align__(16) float s_wn[32 * 100];
    __shared__ __align__(16) float s_wo[64 * 68];    // woutT rows padded to 68
    __shared__ __align__(16) float s_b2[64];
    __shared__ __align__(16) float s_bo[64];
    __shared__ __align__(16) float s_in[16][2][96];
    __shared__ __align__(16) float s_z2[16][64];
    __shared__ float s_ip[16], s_iq[16];

    int tid = threadIdx.x;
    for (int idx = tid; idx < 96 * 32; idx += 256) {
        int i = idx >> 5, j = idx & 31;
        s_wp[j * 100 + i] = w2p[idx];
        s_wn[j * 100 + i] = w2n[idx];
    }
    for (int idx = tid; idx < 64 * 64; idx += 256) {
        int i = idx >> 6, j = idx & 63;
        s_wo[j * 68 + i] = wout[idx];
    }
    if (tid < 32) { s_b2[tid] = b2p[tid]; s_b2[32 + tid] = b2n[tid]; }
    if (tid < 64) s_bo[tid] = bout[tid];
    __syncthreads();

    int ntiles = (n + 15) >> 4;
    int warp = tid >> 5, lane = tid & 31;
    int grp = warp >> 1, half = warp & 1;

    for (int tile = blockIdx.x; tile < ntiles; tile += gridDim.x) {
        int n0 = tile * 16;
        if (tid < 16) {
            int node = n0 + tid;
            if (node < n) {
                s_ip[tid] = 1.0f / fmaxf(g_degp[node], 1e-12f);
                s_iq[tid] = 1.0f / fmaxf(g_degn[node], 1e-12f);
            }
        }
        __syncthreads();
        // stage the two 96-dim concat inputs per node; zero agg+deg after read
        for (int idx = tid; idx < 16 * 192; idx += 256) {
            int nn = idx / 192;
            int r = idx - nn * 192;
            int h = r / 96;
            int i = r - h * 96;
            int node = n0 + nn;
            if (node < n) {
                int base = node * 64;
                float v;
                if (i < 32) {
                    int col = h ? 32 + i : i;      // both halves cover cols 0..63
                    v = g_aggp[base + col] * s_ip[nn];
                    g_aggp[base + col] = 0.f;
                } else if (i < 64) {
                    int col = h ? i - 32 : i;      // both halves cover cols 0..63
                    v = g_aggn[base + col] * s_iq[nn];
                    g_aggn[base + col] = 0.f;
                } else {
                    v = g_z[base + (h ? i - 32 : i - 64)];
                }
                s_in[nn][h][i] = v;
                if (h == 0 && i == 0) { g_degp[node] = 0.f; g_degn[node] = 0.f; }
            }
        }
        __syncthreads();

        {   // z2 = tanh(concat @ w2 + b2)
            const float* row = (half ? s_wn : s_wp) + lane * 100;
            int nb = grp * 4;
            float acc0 = s_b2[half * 32 + lane];
            float acc1 = acc0, acc2 = acc0, acc3 = acc0;
            #pragma unroll
            for (int i = 0; i < 96; i += 4) {
                float4 wv = *(const float4*)(row + i);
                float4 v0 = *(const float4*)(&s_in[nb + 0][half][i]);
                float4 v1 = *(const float4*)(&s_in[nb + 1][half][i]);
                float4 v2 = *(const float4*)(&s_in[nb + 2][half][i]);
                float4 v3 = *(const float4*)(&s_in[nb + 3][half][i]);
                acc0 += wv.x * v0.x + wv.y * v0.y + wv.z * v0.z + wv.w * v0.w;
                acc1 += wv.x * v1.x + wv.y * v1.y + wv.z * v1.z + wv.w * v1.w;
                acc2 += wv.x * v2.x + wv.y * v2.y + wv.z * v2.z + wv.w * v2.w;
                acc3 += wv.x * v3.x + wv.y * v3.y + wv.z * v3.z + wv.w * v3.w;
            }
            int jo = half * 32 + lane;
            s_z2[nb + 0][jo] = tanhf(acc0);
            s_z2[nb + 1][jo] = tanhf(acc1);
            s_z2[nb + 2][jo] = tanhf(acc2);
            s_z2[nb + 3][jo] = tanhf(acc3);
        }
        __syncthreads();

        {   // out = tanh(z2 @ wout + bout)
            int jo = half * 32 + lane;
            const float* row = s_wo + jo * 68;
            int nb = grp * 4;
            float acc0 = s_bo[jo];
            float acc1 = acc0, acc2 = acc0, acc3 = acc0;
            #pragma unroll
            for (int i = 0; i < 64; i += 4) {
                float4 wv = *(const float4*)(row + i);
                float4 v0 = *(const float4*)(&s_z2[nb + 0][i]);
                float4 v1 = *(const float4*)(&s_z2[nb + 1][i]);
                float4 v2 = *(const float4*)(&s_z2[nb + 2][i]);
                float4 v3 = *(const float4*)(&s_z2[nb + 3][i]);
                acc0 += wv.x * v0.x + wv.y * v0.y + wv.z * v0.z + wv.w * v0.w;
                acc1 += wv.x * v1.x + wv.y * v1.y + wv.z * v1.z + wv.w * v1.w;
                acc2 += wv.x * v2.x + wv.y * v2.y + wv.z * v2.z + wv.w * v2.w;
                acc3 += wv.x * v3.x + wv.y * v3.y + wv.z * v3.z + wv.w * v3.w;
            }
            if (n0 + nb + 0 < n) out[(n0 + nb + 0) * 64 + jo] = tanhf(acc0);
            if (n0 + nb + 1 < n) out[(n0 + nb + 1) * 64 + jo] = tanhf(acc1);
            if (n0 + nb + 2 < n) out[(n0 + nb + 2) * 64 + jo] = tanhf(acc2);
            if (n0 + nb + 3 < n) out[(n0 + nb + 3) * 64 + jo] = tanhf(acc3);
        }
        __syncthreads();
    }
}

// ---------------------------------------------------------------------------
extern "C" void kernel_launch(void* const* d_in, const int* in_sizes, int n_in,
                              void* d_out, int out_size) {
    const int*   pei  = (const int*)d_in[0];
    const int*   nei  = (const int*)d_in[1];
    const float* pw   = (const float*)d_in[2];
    const float* nw   = (const float*)d_in[3];
    const float* x    = (const float*)d_in[4];
    const float* w1p  = (const float*)d_in[5];
    const float* b1p  = (const float*)d_in[6];
    const float* w1n  = (const float*)d_in[7];
    const float* b1n  = (const float*)d_in[8];
    const float* w2p  = (const float*)d_in[9];
    const float* b2p  = (const float*)d_in[10];
    const float* w2n  = (const float*)d_in[11];
    const float* b2n  = (const float*)d_in[12];
    const float* wout = (const float*)d_in[13];
    const float* bout = (const float*)d_in[14];
    float* out = (float*)d_out;

    int Ep = in_sizes[2];
    int En = in_sizes[3];
    int n  = in_sizes[4] / 64;

    float *aggp, *aggn, *degp, *degn, *zb;
    cudaGetSymbolAddress((void**)&aggp, g_aggp);
    cudaGetSymbolAddress((void**)&aggn, g_aggn);
    cudaGetSymbolAddress((void**)&degp, g_degp);
    cudaGetSymbolAddress((void**)&degn, g_degn);
    cudaGetSymbolAddress((void**)&zb,   g_z);

    int ga = (int)(((long long)(Ep + En) * 16 + 255) / 256);

    // Round 1 aggregation (pos+neg fused; computes deg); buffers arrive zeroed.
    agg_kernel<<<ga, 256>>>(pei, nei, pw, nw, x,
                            aggp, aggn, degp, degn, Ep, En, 1);
    layer1_kernel<<<MM_GRID, 256>>>(x, w1p, b1p, w1n, b1n, n);
    // Round 2 aggregation (deg unchanged, reused).
    agg_kernel<<<ga, 256>>>(pei, nei, pw, nw, zb,
                            aggp, aggn, degp, degn, Ep, En, 0);
    layer2_kernel<<<MM_GRID, 256>>>(w2p, b2p, w2n, b2n, wout, bout, out, n);
}

// round 15
// speedup vs baseline: 1.8774x; 1.8774x over previous
#include <cuda_runtime.h>
#include <math.h>

#define NMAX 100000

// Scratch (device globals: zero-initialized at module load; every launch
// leaves agg/deg zeroed again, so no zero-pass kernel is needed).
__device__ __align__(16) float g_aggp[NMAX * 64];
__device__ __align__(16) float g_aggn[NMAX * 64];
__device__ __align__(16) float g_degp[NMAX];
__device__ __align__(16) float g_degn[NMAX];
__device__ __align__(16) float g_z[NMAX * 64];
__device__ __align__(16) float g_z2[NMAX * 64];

// ---------------------------------------------------------------------------
// Weighted scatter aggregation, pos+neg fused in one grid: 16 threads/edge,
// float4 per thread.  sum[dst] += feat[src]*w ; (round 1 only) deg[dst] += w.
// red.global.add.v4.f32 (sm_90+): 4x fewer atomic instructions, no return.
// UNCHANGED (control; agg+layer1 together ~233us in the round-5 measurement).
// ---------------------------------------------------------------------------
__global__ void agg_kernel(const int* __restrict__ pei, const int* __restrict__ nei,
                           const float* __restrict__ pw, const float* __restrict__ nw,
                           const float* __restrict__ feat,
                           float* __restrict__ aggp, float* __restrict__ aggn,
                           float* __restrict__ degp, float* __restrict__ degn,
                           int Ep, int En, int do_deg) {
    int tid = blockIdx.x * blockDim.x + threadIdx.x;
    int e = tid >> 4;
    if (e >= Ep + En) return;
    int t = tid & 15;

    const int* ei; const float* wgt; float* sum; float* deg; int E;
    if (e < Ep) { ei = pei; wgt = pw; sum = aggp; deg = degp; E = Ep; }
    else        { e -= Ep; ei = nei; wgt = nw; sum = aggn; deg = degn; E = En; }

    int s = ei[e];
    int d = ei[e + E];
    float w = __ldg(wgt + e);
    float4 v = *(const float4*)(feat + s * 64 + t * 4);
    float a = v.x * w, b = v.y * w, c = v.z * w, dd = v.w * w;
    float* p = sum + d * 64 + t * 4;
    asm volatile("red.global.add.v4.f32 [%0], {%1,%2,%3,%4};"
                 :: "l"(p), "f"(a), "f"(b), "f"(c), "f"(dd) : "memory");
    if (do_deg && t == 0) {
        asm volatile("red.global.add.f32 [%0], %1;"
                     :: "l"(deg + d), "f"(w) : "memory");
    }
}

// ---------------------------------------------------------------------------
// Layer 1: zp = [ap|x] @ w1p + b1p, zn = [an|x] @ w1n + b1n,
//          z = tanh([zp|zn]) -> g_z. Re-zeroes agg (NOT deg) for round 2.
// Staging: 3 coalesced float4 iterations/thread, no div/mod, no divergence.
// GEMM: 16-node tiles, 4-node register blocking, weight rows padded to 132
// (132 mod 32 = 4 -> conflict-free per-quad lanes).
// ---------------------------------------------------------------------------
__global__ void __launch_bounds__(256) layer1_kernel(
    const float* __restrict__ x,
    const float* __restrict__ w1p, const float* __restrict__ b1p,
    const float* __restrict__ w1n, const float* __restrict__ b1n,
    int n)
{
    __shared__ __align__(16) float s_wp[32 * 132];
    __shared__ __align__(16) float s_wn[32 * 132];
    __shared__ __align__(16) float s_b[64];
    __shared__ __align__(16) float s_ap[16][64];
    __shared__ __align__(16) float s_an[16][64];
    __shared__ __align__(16) float s_x[16][64];
    __shared__ float s_ip[16], s_iq[16];

    int tid = threadIdx.x;
    for (int idx = tid; idx < 128 * 32; idx += 256) {
        int i = idx >> 5, j = idx & 31;
        s_wp[j * 132 + i] = w1p[idx];
        s_wn[j * 132 + i] = w1n[idx];
    }
    if (tid < 32) { s_b[tid] = b1p[tid]; s_b[32 + tid] = b1n[tid]; }
    __syncthreads();

    int ntiles = (n + 15) >> 4;
    int warp = tid >> 5, lane = tid & 31;
    int grp = warp >> 1, half = warp & 1;
    int nn = tid >> 4, q = tid & 15;        // staging coords: node, quad

    for (int tile = blockIdx.x; tile < ntiles; tile += gridDim.x) {
        int n0 = tile * 16;
        // Phase A: inverse degrees (single reader per value)
        if (tid < 16) {
            int node = n0 + tid;
            if (node < n) {
                s_ip[tid] = 1.0f / fmaxf(g_degp[node], 1e-12f);
                s_iq[tid] = 1.0f / fmaxf(g_degn[node], 1e-12f);
            }
        }
        __syncthreads();
        // Phase B: coalesced float4 staging; zero agg after read
        if (n0 + nn < n) {
            int o = (n0 + nn) * 64 + q * 4;
            float4 z4 = make_float4(0.f, 0.f, 0.f, 0.f);
            float4 a4 = *(const float4*)(g_aggp + o);
            float ip = s_ip[nn];
            a4.x *= ip; a4.y *= ip; a4.z *= ip; a4.w *= ip;
            *(float4*)(&s_ap[nn][q * 4]) = a4;
            *(float4*)(g_aggp + o) = z4;

            float4 b4 = *(const float4*)(g_aggn + o);
            float iq = s_iq[nn];
            b4.x *= iq; b4.y *= iq; b4.z *= iq; b4.w *= iq;
            *(float4*)(&s_an[nn][q * 4]) = b4;
            *(float4*)(g_aggn + o) = z4;

            *(float4*)(&s_x[nn][q * 4]) = *(const float4*)(x + o);
        }
        __syncthreads();

        {
            const float* row = (half ? s_wn : s_wp) + lane * 132;
            const float (*inA)[64] = half ? s_an : s_ap;
            int nb = grp * 4;
            float acc0 = s_b[half * 32 + lane];
            float acc1 = acc0, acc2 = acc0, acc3 = acc0;
            #pragma unroll
            for (int i = 0; i < 64; i += 4) {
                float4 wv = *(const float4*)(row + i);
                float4 v0 = *(const float4*)(&inA[nb + 0][i]);
                float4 v1 = *(const float4*)(&inA[nb + 1][i]);
                float4 v2 = *(const float4*)(&inA[nb + 2][i]);
                float4 v3 = *(const float4*)(&inA[nb + 3][i]);
                acc0 += wv.x * v0.x + wv.y * v0.y + wv.z * v0.z + wv.w * v0.w;
                acc1 += wv.x * v1.x + wv.y * v1.y + wv.z * v1.z + wv.w * v1.w;
                acc2 += wv.x * v2.x + wv.y * v2.y + wv.z * v2.z + wv.w * v2.w;
                acc3 += wv.x * v3.x + wv.y * v3.y + wv.z * v3.z + wv.w * v3.w;
            }
            #pragma unroll
            for (int i = 0; i < 64; i += 4) {
                float4 wv = *(const float4*)(row + 64 + i);
                float4 v0 = *(const float4*)(&s_x[nb + 0][i]);
                float4 v1 = *(const float4*)(&s_x[nb + 1][i]);
                float4 v2 = *(const float4*)(&s_x[nb + 2][i]);
                float4 v3 = *(const float4*)(&s_x[nb + 3][i]);
                acc0 += wv.x * v0.x + wv.y * v0.y + wv.z * v0.z + wv.w * v0.w;
                acc1 += wv.x * v1.x + wv.y * v1.y + wv.z * v1.z + wv.w * v1.w;
                acc2 += wv.x * v2.x + wv.y * v2.y + wv.z * v2.z + wv.w * v2.w;
                acc3 += wv.x * v3.x + wv.y * v3.y + wv.z * v3.z + wv.w * v3.w;
            }
            int jo = half * 32 + lane;
            if (n0 + nb + 0 < n) g_z[(n0 + nb + 0) * 64 + jo] = tanhf(acc0);
            if (n0 + nb + 1 < n) g_z[(n0 + nb + 1) * 64 + jo] = tanhf(acc1);
            if (n0 + nb + 2 < n) g_z[(n0 + nb + 2) * 64 + jo] = tanhf(acc2);
            if (n0 + nb + 3 < n) g_z[(n0 + nb + 3) * 64 + jo] = tanhf(acc3);
        }
        __syncthreads();
    }
}

// ---------------------------------------------------------------------------
// Layer 2a: z2 = tanh(concat @ w2 + b2) -> g_z2.
//  op (h=0) input: [aggp·ip cols 0..31 | aggn·iq cols 32..63 | z cols 0..31]
//  on (h=1) input: [aggp·ip cols 32..63 | aggn·iq cols 0..31 | z cols 32..63]
// Concat permutation = pointer offsets (half*32 / (1-half)*32) on three plain
// [16][64] shared arrays staged with coalesced float4 (3 iters/thread,
// no div/mod, no divergence). Zeroes agg+deg after read (restores
// launch-entry invariant for graph replay).
// ---------------------------------------------------------------------------
__global__ void __launch_bounds__(256) layer2a_kernel(
    const float* __restrict__ w2p, const float* __restrict__ b2p,
    const float* __restrict__ w2n, const float* __restrict__ b2n,
    int n)
{
    __shared__ __align__(16) float s_wp[32 * 100];   // w2pT rows padded to 100
    __shared__ __align__(16) float s_wn[32 * 100];
    __shared__ __align__(16) float s_b2[64];
    __shared__ __align__(16) float s_A[16][64];      // aggp * ip
    __shared__ __align__(16) float s_B[16][64];      // aggn * iq
    __shared__ __align__(16) float s_Z[16][64];      // z
    __shared__ float s_ip[16], s_iq[16];

    int tid = threadIdx.x;
    for (int idx = tid; idx < 96 * 32; idx += 256) {
        int i = idx >> 5, j = idx & 31;
        s_wp[j * 100 + i] = w2p[idx];
        s_wn[j * 100 + i] = w2n[idx];
    }
    if (tid < 32) { s_b2[tid] = b2p[tid]; s_b2[32 + tid] = b2n[tid]; }
    __syncthreads();

    int ntiles = (n + 15) >> 4;
    int warp = tid >> 5, lane = tid & 31;
    int grp = warp >> 1, half = warp & 1;
    int nn = tid >> 4, q = tid & 15;

    for (int tile = blockIdx.x; tile < ntiles; tile += gridDim.x) {
        int n0 = tile * 16;
        if (tid < 16) {
            int node = n0 + tid;
            if (node < n) {
                s_ip[tid] = 1.0f / fmaxf(g_degp[node], 1e-12f);
                s_iq[tid] = 1.0f / fmaxf(g_degn[node], 1e-12f);
            }
        }
        __syncthreads();
        // Coalesced staging; zero agg+deg after read
        if (n0 + nn < n) {
            int o = (n0 + nn) * 64 + q * 4;
            float4 z4 = make_float4(0.f, 0.f, 0.f, 0.f);
            float4 a4 = *(const float4*)(g_aggp + o);
            float ip = s_ip[nn];
            a4.x *= ip; a4.y *= ip; a4.z *= ip; a4.w *= ip;
            *(float4*)(&s_A[nn][q * 4]) = a4;
            *(float4*)(g_aggp + o) = z4;

            float4 b4 = *(const float4*)(g_aggn + o);
            float iq = s_iq[nn];
            b4.x *= iq; b4.y *= iq; b4.z *= iq; b4.w *= iq;
            *(float4*)(&s_B[nn][q * 4]) = b4;
            *(float4*)(g_aggn + o) = z4;

            *(float4*)(&s_Z[nn][q * 4]) = *(const float4*)(g_z + o);
            if (q == 0) { g_degp[n0 + nn] = 0.f; g_degn[n0 + nn] = 0.f; }
        }
        __syncthreads();

        {
            const float* row = (half ? s_wn : s_wp) + lane * 100;
            int nb = grp * 4;
            int oA = half * 32;          // aggp/z slice for this half
            int oB = 32 - oA;            // aggn slice is the opposite half
            float acc0 = s_b2[half * 32 + lane];
            float acc1 = acc0, acc2 = acc0, acc3 = acc0;
            #pragma unroll
            for (int i = 0; i < 32; i += 4) {
                float4 wv = *(const float4*)(row + i);
                float4 v0 = *(const float4*)(&s_A[nb + 0][oA + i]);
                float4 v1 = *(const float4*)(&s_A[nb + 1][oA + i]);
                float4 v2 = *(const float4*)(&s_A[nb + 2][oA + i]);
                float4 v3 = *(const float4*)(&s_A[nb + 3][oA + i]);
                acc0 += wv.x * v0.x + wv.y * v0.y + wv.z * v0.z + wv.w * v0.w;
                acc1 += wv.x * v1.x + wv.y * v1.y + wv.z * v1.z + wv.w * v1.w;
                acc2 += wv.x * v2.x + wv.y * v2.y + wv.z * v2.z + wv.w * v2.w;
                acc3 += wv.x * v3.x + wv.y * v3.y + wv.z * v3.z + wv.w * v3.w;
            }
            #pragma unroll
            for (int i = 0; i < 32; i += 4) {
                float4 wv = *(const float4*)(row + 32 + i);
                float4 v0 = *(const float4*)(&s_B[nb + 0][oB + i]);
                float4 v1 = *(const float4*)(&s_B[nb + 1][oB + i]);
                float4 v2 = *(const float4*)(&s_B[nb + 2][oB + i]);
                float4 v3 = *(const float4*)(&s_B[nb + 3][oB + i]);
                acc0 += wv.x * v0.x + wv.y * v0.y + wv.z * v0.z + wv.w * v0.w;
                acc1 += wv.x * v1.x + wv.y * v1.y + wv.z * v1.z + wv.w * v1.w;
                acc2 += wv.x * v2.x + wv.y * v2.y + wv.z * v2.z + wv.w * v2.w;
                acc3 += wv.x * v3.x + wv.y * v3.y + wv.z * v3.z + wv.w * v3.w;
            }
            #pragma unroll
            for (int i = 0; i < 32; i += 4) {
                float4 wv = *(const float4*)(row + 64 + i);
                float4 v0 = *(const float4*)(&s_Z[nb + 0][oA + i]);
                float4 v1 = *(const float4*)(&s_Z[nb + 1][oA + i]);
                float4 v2 = *(const float4*)(&s_Z[nb + 2][oA + i]);
                float4 v3 = *(const float4*)(&s_Z[nb + 3][oA + i]);
                acc0 += wv.x * v0.x + wv.y * v0.y + wv.z * v0.z + wv.w * v0.w;
                acc1 += wv.x * v1.x + wv.y * v1.y + wv.z * v1.z + wv.w * v1.w;
                acc2 += wv.x * v2.x + wv.y * v2.y + wv.z * v2.z + wv.w * v2.w;
                acc3 += wv.x * v3.x + wv.y * v3.y + wv.z * v3.z + wv.w * v3.w;
            }
            int jo = half * 32 + lane;
            if (n0 + nb + 0 < n) g_z2[(n0 + nb + 0) * 64 + jo] = tanhf(acc0);
            if (n0 + nb + 1 < n) g_z2[(n0 + nb + 1) * 64 + jo] = tanhf(acc1);
            if (n0 + nb + 2 < n) g_z2[(n0 + nb + 2) * 64 + jo] = tanhf(acc2);
            if (n0 + nb + 3 < n) g_z2[(n0 + nb + 3) * 64 + jo] = tanhf(acc3);
        }
        __syncthreads();
    }
}

// ---------------------------------------------------------------------------
// Layer 2b: out = tanh(z2 @ wout + bout).  64x64 GEMM, ~21.5KB smem ->
// 8 blocks/SM (thread-capped) = 64 warps, 100% occupancy; grid 1184 = 1 wave.
// ---------------------------------------------------------------------------
__global__ void __launch_bounds__(256) layer2b_kernel(
    const float* __restrict__ wout, const float* __restrict__ bout,
    float* __restrict__ out, int n)
{
    __shared__ __align__(16) float s_wo[64 * 68];    // woutT rows padded to 68
    __shared__ __align__(16) float s_bo[64];
    __shared__ __align__(16) float s_z2[16][64];

    int tid = threadIdx.x;
    for (int idx = tid; idx < 64 * 64; idx += 256) {
        int i = idx >> 6, j = idx & 63;
        s_wo[j * 68 + i] = wout[idx];
    }
    if (tid < 64) s_bo[tid] = bout[tid];
    __syncthreads();

    int ntiles = (n + 15) >> 4;
    int warp = tid >> 5, lane = tid & 31;
    int grp = warp >> 1, half = warp & 1;
    int nn = tid >> 4, q = tid & 15;

    for (int tile = blockIdx.x; tile < ntiles; tile += gridDim.x) {
        int n0 = tile * 16;
        if (n0 + nn < n)
            *(float4*)(&s_z2[nn][q * 4]) =
                *(const float4*)(&g_z2[(n0 + nn) * 64 + q * 4]);
        __syncthreads();

        {
            int jo = half * 32 + lane;
            const float* row = s_wo + jo * 68;
            int nb = grp * 4;
            float acc0 = s_bo[jo];
            float acc1 = acc0, acc2 = acc0, acc3 = acc0;
            #pragma unroll
            for (int i = 0; i < 64; i += 4) {
                float4 wv = *(const float4*)(row + i);
                float4 v0 = *(const float4*)(&s_z2[nb + 0][i]);
                float4 v1 = *(const float4*)(&s_z2[nb + 1][i]);
                float4 v2 = *(const float4*)(&s_z2[nb + 2][i]);
                float4 v3 = *(const float4*)(&s_z2[nb + 3][i]);
                acc0 += wv.x * v0.x + wv.y * v0.y + wv.z * v0.z + wv.w * v0.w;
                acc1 += wv.x * v1.x + wv.y * v1.y + wv.z * v1.z + wv.w * v1.w;
                acc2 += wv.x * v2.x + wv.y * v2.y + wv.z * v2.z + wv.w * v2.w;
                acc3 += wv.x * v3.x + wv.y * v3.y + wv.z * v3.z + wv.w * v3.w;
            }
            if (n0 + nb + 0 < n) out[(n0 + nb + 0) * 64 + jo] = tanhf(acc0);
            if (n0 + nb + 1 < n) out[(n0 + nb + 1) * 64 + jo] = tanhf(acc1);
            if (n0 + nb + 2 < n) out[(n0 + nb + 2) * 64 + jo] = tanhf(acc2);
            if (n0 + nb + 3 < n) out[(n0 + nb + 3) * 64 + jo] = tanhf(acc3);
        }
        __syncthreads();
    }
}

// ---------------------------------------------------------------------------
extern "C" void kernel_launch(void* const* d_in, const int* in_sizes, int n_in,
                              void* d_out, int out_size) {
    const int*   pei  = (const int*)d_in[0];
    const int*   nei  = (const int*)d_in[1];
    const float* pw   = (const float*)d_in[2];
    const float* nw   = (const float*)d_in[3];
    const float* x    = (const float*)d_in[4];
    const float* w1p  = (const float*)d_in[5];
    const float* b1p  = (const float*)d_in[6];
    const float* w1n  = (const float*)d_in[7];
    const float* b1n  = (const float*)d_in[8];
    const float* w2p  = (const float*)d_in[9];
    const float* b2p  = (const float*)d_in[10];
    const float* w2n  = (const float*)d_in[11];
    const float* b2n  = (const float*)d_in[12];
    const float* wout = (const float*)d_in[13];
    const float* bout = (const float*)d_in[14];
    float* out = (float*)d_out;

    int Ep = in_sizes[2];
    int En = in_sizes[3];
    int n  = in_sizes[4] / 64;

    float *aggp, *aggn, *degp, *degn, *zb;
    cudaGetSymbolAddress((void**)&aggp, g_aggp);
    cudaGetSymbolAddress((void**)&aggn, g_aggn);
    cudaGetSymbolAddress((void**)&degp, g_degp);
    cudaGetSymbolAddress((void**)&degn, g_degn);
    cudaGetSymbolAddress((void**)&zb,   g_z);

    int ga = (int)(((long long)(Ep + En) * 16 + 255) / 256);

    // Round 1 aggregation (pos+neg fused; computes deg); buffers arrive zeroed.
    agg_kernel<<<ga, 256>>>(pei, nei, pw, nw, x,
                            aggp, aggn, degp, degn, Ep, En, 1);
    layer1_kernel<<<888, 256>>>(x, w1p, b1p, w1n, b1n, n);
    // Round 2 aggregation (deg unchanged, reused).
    agg_kernel<<<ga, 256>>>(pei, nei, pw, nw, zb,
                            aggp, aggn, degp, degn, Ep, En, 0);
    layer2a_kernel<<<740, 256>>>(w2p, b2p, w2n, b2n, n);
    layer2b_kernel<<<1184, 256>>>(wout, bout, out, n);
}